// round 4
// baseline (speedup 1.0000x reference)
#include <cuda_runtime.h>
#include <cstdint>

#define SEQ  4096
#define HID  1024
#define NCLS 256

typedef unsigned long long ull;

// ---------------- scratch (device globals) ----------------
__device__ float g_table[NCLS * 4 * HID];   //  4 MB  layer0 pre-activation table
__device__ float g_pre1 [SEQ  * 4 * HID];   // 64 MB  layer1 pre (GEMM output)
__device__ float g_hs0  [SEQ * HID];        // 16 MB  h0 (GEMM input)
__device__ float g_hs1  [SEQ * HID];        // 16 MB  h1 (finals)
__device__ ull   g_tg0  [SEQ * HID];        // 32 MB  tagged h0 handoff
__device__ ull   g_tg1  [SEQ * HID];        // 32 MB  tagged h1 handoff
__device__ ull   g_tg2  [SEQ * NCLS];       //  8 MB  tagged h2 handoff
__device__ float g_cfin [2 * HID + NCLS];   // c0, c1, c2 finals
__device__ unsigned int g_gen;

// ---------------- helpers ----------------
__device__ __forceinline__ float fsig(float x) {
    return __fdividef(1.0f, 1.0f + __expf(-x));
}
__device__ __forceinline__ ull ld_tag(const ull* p) {
    ull v;
    asm volatile("ld.relaxed.gpu.global.b64 %0, [%1];" : "=l"(v) : "l"(p) : "memory");
    return v;
}
__device__ __forceinline__ void st_tag(ull* p, ull v) {
    asm volatile("st.relaxed.gpu.global.b64 [%0], %1;" :: "l"(p), "l"(v) : "memory");
}
__device__ __forceinline__ ull fma2(ull a, ull b, ull c) {
    ull d;
    asm("fma.rn.f32x2 %0, %1, %2, %3;" : "=l"(d) : "l"(a), "l"(b), "l"(c));
    return d;
}
__device__ __forceinline__ ull add2(ull a, ull b) {
    ull d;
    asm("add.rn.f32x2 %0, %1, %2;" : "=l"(d) : "l"(a), "l"(b));
    return d;
}
__device__ __forceinline__ ull pack2(float lo, float hi) {
    ull d;
    asm("mov.b64 %0, {%1, %2};" : "=l"(d) : "f"(lo), "f"(hi));
    return d;
}
__device__ __forceinline__ float lo32(ull v) { return __uint_as_float((unsigned)v); }
__device__ __forceinline__ float hi32(ull v) { return __uint_as_float((unsigned)(v >> 32)); }

__global__ void bump_gen_kernel() { if (threadIdx.x == 0) g_gen += 1u; }

// batch-poll 4 tagged words (indices i0..i0+3 strides st) until all carry tag
#define POLL4(src, i0, st, expect, d0, d1, d2, d3)                              \
    {                                                                           \
        ull _v0 = ld_tag((src) + (i0));                                         \
        ull _v1 = ld_tag((src) + (i0) + (st));                                  \
        ull _v2 = ld_tag((src) + (i0) + 2 * (st));                              \
        ull _v3 = ld_tag((src) + (i0) + 3 * (st));                              \
        while (!(((unsigned)(_v0 >> 32) == (expect)) &                          \
                 ((unsigned)(_v1 >> 32) == (expect)) &                          \
                 ((unsigned)(_v2 >> 32) == (expect)) &                          \
                 ((unsigned)(_v3 >> 32) == (expect)))) {                        \
            _v0 = ld_tag((src) + (i0));                                         \
            _v1 = ld_tag((src) + (i0) + (st));                                  \
            _v2 = ld_tag((src) + (i0) + 2 * (st));                              \
            _v3 = ld_tag((src) + (i0) + 3 * (st));                              \
        }                                                                       \
        d0 = __uint_as_float((unsigned)_v0);                                    \
        d1 = __uint_as_float((unsigned)_v1);                                    \
        d2 = __uint_as_float((unsigned)_v2);                                    \
        d3 = __uint_as_float((unsigned)_v3);                                    \
    }

// ---------------- GEMM:  C[M][N] = A[M][K] @ B[N][K]^T + b1[N] + b2[N] -----
// 128x64 tile, 256 threads, 8x4 accumulators.
template<int WHICH>
__global__ void __launch_bounds__(256)
gemm_bias(const float* __restrict__ Ain, const float* __restrict__ B,
          const float* __restrict__ b1, const float* __restrict__ b2,
          int M, int N, int K)
{
    const float* A = (WHICH == 1) ? g_hs0 : Ain;
    float*       C = (WHICH == 0) ? g_table : g_pre1;

    __shared__ float As[16][136];
    __shared__ float Bs[16][72];

    const int m0 = blockIdx.y * 128;
    const int n0 = blockIdx.x * 64;
    const int tid = threadIdx.x;
    const int tm = tid >> 4;
    const int tn = tid & 15;
    const int lra = tid >> 1;
    const int lka = (tid & 1) * 8;
    const int lrb = tid >> 2;
    const int lkb = (tid & 3) * 4;

    float acc[8][4];
#pragma unroll
    for (int i = 0; i < 8; i++)
#pragma unroll
        for (int j = 0; j < 4; j++) acc[i][j] = 0.0f;

    for (int kt = 0; kt < K; kt += 16) {
        float4 a0 = *reinterpret_cast<const float4*>(&A[(size_t)(m0 + lra) * K + kt + lka]);
        float4 a1 = *reinterpret_cast<const float4*>(&A[(size_t)(m0 + lra) * K + kt + lka + 4]);
        float4 bv = *reinterpret_cast<const float4*>(&B[(size_t)(n0 + lrb) * K + kt + lkb]);
        __syncthreads();
        As[lka + 0][lra] = a0.x; As[lka + 1][lra] = a0.y; As[lka + 2][lra] = a0.z; As[lka + 3][lra] = a0.w;
        As[lka + 4][lra] = a1.x; As[lka + 5][lra] = a1.y; As[lka + 6][lra] = a1.z; As[lka + 7][lra] = a1.w;
        Bs[lkb + 0][lrb] = bv.x; Bs[lkb + 1][lrb] = bv.y; Bs[lkb + 2][lrb] = bv.z; Bs[lkb + 3][lrb] = bv.w;
        __syncthreads();
#pragma unroll
        for (int kk = 0; kk < 16; kk++) {
            float4 a4 = *reinterpret_cast<const float4*>(&As[kk][tm * 8]);
            float4 a5 = *reinterpret_cast<const float4*>(&As[kk][tm * 8 + 4]);
            float4 b4 = *reinterpret_cast<const float4*>(&Bs[kk][tn * 4]);
            float a[8] = {a4.x, a4.y, a4.z, a4.w, a5.x, a5.y, a5.z, a5.w};
            float b[4] = {b4.x, b4.y, b4.z, b4.w};
#pragma unroll
            for (int i = 0; i < 8; i++)
#pragma unroll
                for (int j = 0; j < 4; j++) acc[i][j] += a[i] * b[j];
        }
    }

    const int col0 = n0 + tn * 4;
    float4 v1 = *reinterpret_cast<const float4*>(&b1[col0]);
    float4 v2 = *reinterpret_cast<const float4*>(&b2[col0]);
    float bias[4] = {v1.x + v2.x, v1.y + v2.y, v1.z + v2.z, v1.w + v2.w};
#pragma unroll
    for (int i = 0; i < 8; i++) {
        int row = m0 + tm * 8 + i;
        float4 o;
        o.x = acc[i][0] + bias[0];
        o.y = acc[i][1] + bias[1];
        o.z = acc[i][2] + bias[2];
        o.w = acc[i][3] + bias[3];
        *reinterpret_cast<float4*>(&C[(size_t)row * N + col0]) = o;
    }
}

// ============ layer-0 scan: 128 CTAs x 256 thr, warp-per-output ============
// lane: g2 = l>>4 selects gate pair {2*g2, 2*g2+1}; sub = l&15 selects a
// 64-float contiguous k-slice. Reduce = 4 packed-f32x2 xor stages + gathers.
__global__ void __launch_bounds__(256, 1)
lstm_scan0(const float* __restrict__ whh, const int* __restrict__ tokens)
{
    const int tid = threadIdx.x;
    const int w = tid >> 5;
    const int l = tid & 31;
    const int g2 = l >> 4;
    const int sub = l & 15;
    const int out = blockIdx.x * 8 + w;
    const unsigned tb = g_gen * (unsigned)(SEQ + 1);
    const int ra = 2 * g2, rb = ra + 1;

    __shared__ __align__(16) float sh[2][HID];
    __shared__ int stok[SEQ];

    ulonglong2 wA[16], wB[16];
    {
        const ulonglong2* pa = reinterpret_cast<const ulonglong2*>(
            whh + (size_t)(ra * HID + out) * HID + sub * 64);
        const ulonglong2* pb = reinterpret_cast<const ulonglong2*>(
            whh + (size_t)(rb * HID + out) * HID + sub * 64);
#pragma unroll
        for (int i = 0; i < 16; i++) { wA[i] = pa[i]; wB[i] = pb[i]; }
    }
    for (int i = tid; i < SEQ; i += 256) stok[i] = tokens[i];
    for (int i = tid; i < HID; i += 256) sh[0][i] = 0.0f;
    __syncthreads();

    auto ldpre = [&](int t) -> ull {
        const int tok = stok[t];
        float a = __ldg(&g_table[(size_t)tok * (4 * HID) + ra * HID + out]);
        float b = __ldg(&g_table[(size_t)tok * (4 * HID) + rb * HID + out]);
        return pack2(a, b);
    };

    float c = 0.0f;
    ull pv = ldpre(0);

    for (int t = 0; t < SEQ; t++) {
        ull pvn = (t + 1 < SEQ) ? ldpre(t + 1) : 0ull;
        float* shb = sh[t & 1];
        if (t > 0) {
            const ull* src = g_tg0 + (size_t)(t - 1) * HID;
            const unsigned expect = tb + (unsigned)t;
            float d0, d1, d2, d3;
            POLL4(src, tid, 256, expect, d0, d1, d2, d3);
            shb[tid] = d0; shb[tid + 256] = d1; shb[tid + 512] = d2; shb[tid + 768] = d3;
        }
        __syncthreads();

        const ulonglong2* hv = reinterpret_cast<const ulonglong2*>(shb + sub * 64);
        ull aA = 0ull, aB = 0ull;
#pragma unroll
        for (int i = 0; i < 16; i++) {
            ulonglong2 h4 = hv[i];
            aA = fma2(wA[i].x, h4.x, aA); aA = fma2(wA[i].y, h4.y, aA);
            aB = fma2(wB[i].x, h4.x, aB); aB = fma2(wB[i].y, h4.y, aB);
        }
        ull p = pack2(lo32(aA) + hi32(aA), lo32(aB) + hi32(aB));
        p = add2(p, __shfl_xor_sync(0xffffffffu, p, 8));
        p = add2(p, __shfl_xor_sync(0xffffffffu, p, 4));
        p = add2(p, __shfl_xor_sync(0xffffffffu, p, 2));
        p = add2(p, __shfl_xor_sync(0xffffffffu, p, 1));
        p = add2(p, pv);

        float x0 = lo32(p), x1 = hi32(p);
        float s0 = fsig(g2 ? 2.0f * x0 : x0);
        float a0 = g2 ? (2.0f * s0 - 1.0f) : s0;   // gate2 -> tanh
        float a1 = fsig(x1);

        float gi = __shfl_sync(0xffffffffu, a0, 0);
        float gf = __shfl_sync(0xffffffffu, a1, 0);
        float tg = __shfl_sync(0xffffffffu, a0, 16);
        float go = __shfl_sync(0xffffffffu, a1, 16);

        c = gf * c + gi * tg;
        float h = go * (2.0f * fsig(2.0f * c) - 1.0f);

        if (l == 0) {
            st_tag(g_tg0 + (size_t)t * HID + out,
                   ((ull)(tb + (unsigned)t + 1u) << 32) | (ull)__float_as_uint(h));
            g_hs0[(size_t)t * HID + out] = h;
            if (t == SEQ - 1) g_cfin[out] = c;
        }
        pv = pvn;
    }
}

// ============ fused layer1 + layer2 scan: 128 CTAs x 320 thr ============
// warps 0-7: layer1 output (cta*8+w) consuming g_pre1 + h1 recurrence.
// warps 8-9: layer2 output (cta*2+(w-8)); input matvec w_ih2 @ h1_t (from sh1,
// one iteration lagged) + w_hh2 @ h2_{t-1} (weights in SMEM, h2 via g_tg2).
__global__ void __launch_bounds__(320, 1)
lstm_scan12(const float* __restrict__ whh1, const float* __restrict__ wih2,
            const float* __restrict__ whh2, const float* __restrict__ bih2,
            const float* __restrict__ bhh2, float* __restrict__ outp)
{
    const int tid = threadIdx.x;
    const int w = tid >> 5;
    const int l = tid & 31;
    const int g2 = l >> 4;
    const int sub = l & 15;
    const unsigned tb = g_gen * (unsigned)(SEQ + 1);
    const int ra = 2 * g2, rb = ra + 1;
    const bool isL1 = (w < 8);
    const int out  = blockIdx.x * 8 + w;            // L1 output id
    const int oo   = w - 8;                          // local L2 output (0/1)
    const int out2 = blockIdx.x * 2 + oo;            // L2 output id

    __shared__ __align__(16) float sh1[2][HID];
    __shared__ __align__(16) float sh2[2][NCLS];
    __shared__ __align__(16) float whs[2][4][NCLS];  // w_hh2 slices for 2 outputs

    // register weights: L1 -> w_hh1 rows; L2 -> w_ih2 rows (both 2x64 floats/lane)
    ulonglong2 wA[16], wB[16];
    if (isL1) {
        const ulonglong2* pa = reinterpret_cast<const ulonglong2*>(
            whh1 + (size_t)(ra * HID + out) * HID + sub * 64);
        const ulonglong2* pb = reinterpret_cast<const ulonglong2*>(
            whh1 + (size_t)(rb * HID + out) * HID + sub * 64);
#pragma unroll
        for (int i = 0; i < 16; i++) { wA[i] = pa[i]; wB[i] = pb[i]; }
    } else {
        const ulonglong2* pa = reinterpret_cast<const ulonglong2*>(
            wih2 + (size_t)(ra * NCLS + out2) * HID + sub * 64);
        const ulonglong2* pb = reinterpret_cast<const ulonglong2*>(
            wih2 + (size_t)(rb * NCLS + out2) * HID + sub * 64);
#pragma unroll
        for (int i = 0; i < 16; i++) { wA[i] = pa[i]; wB[i] = pb[i]; }
    }

    // w_hh2 -> SMEM (2 outputs x 4 gates x 256)
    for (int i = tid; i < 2 * 4 * NCLS; i += 320) {
        int o = i >> 10, rem = i & 1023, r = rem >> 8, k = rem & 255;
        whs[o][r][k] = whh2[(size_t)(r * NCLS + blockIdx.x * 2 + o) * NCLS + k];
    }
    for (int i = tid; i < 2 * HID; i += 320)  ((float*)sh1)[i] = 0.0f;
    for (int i = tid; i < 2 * NCLS; i += 320) ((float*)sh2)[i] = 0.0f;
    __syncthreads();

    ull bias2 = 0ull;
    if (!isL1) {
        bias2 = pack2(bih2[ra * NCLS + out2] + bhh2[ra * NCLS + out2],
                      bih2[rb * NCLS + out2] + bhh2[rb * NCLS + out2]);
    }

    auto ldpre1 = [&](int t) -> ull {
        float a = __ldg(&g_pre1[(size_t)t * (4 * HID) + ra * HID + out]);
        float b = __ldg(&g_pre1[(size_t)t * (4 * HID) + rb * HID + out]);
        return pack2(a, b);
    };

    float c1 = 0.0f, c2 = 0.0f;
    ull pv = isL1 ? ldpre1(0) : 0ull;

    for (int it = 0; it <= SEQ; ++it) {
        ull pvn = (isL1 && it + 1 < SEQ) ? ldpre1(it + 1) : 0ull;

        // ---- stage ----
        if (tid < 256) {
            if (it >= 1) {
                const ull* src = g_tg1 + (size_t)(it - 1) * HID;
                const unsigned expect = tb + (unsigned)it;
                float d0, d1, d2, d3;
                POLL4(src, tid, 256, expect, d0, d1, d2, d3);
                float* s1 = sh1[it & 1];
                s1[tid] = d0; s1[tid + 256] = d1; s1[tid + 512] = d2; s1[tid + 768] = d3;
            }
        } else {
            if (it >= 2) {
                const int t2 = tid - 256;
                const ull* src = g_tg2 + (size_t)(it - 2) * NCLS;
                const unsigned expect = tb + (unsigned)(it - 1);
                float d0, d1, d2, d3;
                POLL4(src, t2, 64, expect, d0, d1, d2, d3);
                float* s2 = sh2[it & 1];
                s2[t2] = d0; s2[t2 + 64] = d1; s2[t2 + 128] = d2; s2[t2 + 192] = d3;
            }
        }
        __syncthreads();

        if (isL1) {
            if (it < SEQ) {
                const float* shb = sh1[it & 1];
                const ulonglong2* hv = reinterpret_cast<const ulonglong2*>(shb + sub * 64);
                ull aA = 0ull, aB = 0ull;
#pragma unroll
                for (int i = 0; i < 16; i++) {
                    ulonglong2 h4 = hv[i];
                    aA = fma2(wA[i].x, h4.x, aA); aA = fma2(wA[i].y, h4.y, aA);
                    aB = fma2(wB[i].x, h4.x, aB); aB = fma2(wB[i].y, h4.y, aB);
                }
                ull p = pack2(lo32(aA) + hi32(aA), lo32(aB) + hi32(aB));
                p = add2(p, __shfl_xor_sync(0xffffffffu, p, 8));
                p = add2(p, __shfl_xor_sync(0xffffffffu, p, 4));
                p = add2(p, __shfl_xor_sync(0xffffffffu, p, 2));
                p = add2(p, __shfl_xor_sync(0xffffffffu, p, 1));
                p = add2(p, pv);

                float x0 = lo32(p), x1 = hi32(p);
                float s0 = fsig(g2 ? 2.0f * x0 : x0);
                float a0 = g2 ? (2.0f * s0 - 1.0f) : s0;
                float a1 = fsig(x1);
                float gi = __shfl_sync(0xffffffffu, a0, 0);
                float gf = __shfl_sync(0xffffffffu, a1, 0);
                float tg = __shfl_sync(0xffffffffu, a0, 16);
                float go = __shfl_sync(0xffffffffu, a1, 16);
                c1 = gf * c1 + gi * tg;
                float h = go * (2.0f * fsig(2.0f * c1) - 1.0f);
                if (l == 0) {
                    st_tag(g_tg1 + (size_t)it * HID + out,
                           ((ull)(tb + (unsigned)it + 1u) << 32) | (ull)__float_as_uint(h));
                    g_hs1[(size_t)it * HID + out] = h;
                    if (it == SEQ - 1) g_cfin[HID + out] = c1;
                }
            }
        } else {
            if (it >= 1) {
                const int s = it - 1;
                const float* shb = sh1[it & 1];   // h1_s
                const ulonglong2* hv = reinterpret_cast<const ulonglong2*>(shb + sub * 64);
                ull aA = 0ull, aB = 0ull;
#pragma unroll
                for (int i = 0; i < 16; i++) {
                    ulonglong2 h4 = hv[i];
                    aA = fma2(wA[i].x, h4.x, aA); aA = fma2(wA[i].y, h4.y, aA);
                    aB = fma2(wB[i].x, h4.x, aB); aB = fma2(wB[i].y, h4.y, aB);
                }
                // h2 recurrence part (weights from SMEM)
                const ulonglong2* h2v = reinterpret_cast<const ulonglong2*>(&sh2[it & 1][sub * 16]);
                const ulonglong2* wa2 = reinterpret_cast<const ulonglong2*>(&whs[oo][ra][sub * 16]);
                const ulonglong2* wb2 = reinterpret_cast<const ulonglong2*>(&whs[oo][rb][sub * 16]);
#pragma unroll
                for (int i = 0; i < 4; i++) {
                    ulonglong2 h4 = h2v[i];
                    ulonglong2 va = wa2[i], vb = wb2[i];
                    aA = fma2(va.x, h4.x, aA); aA = fma2(va.y, h4.y, aA);
                    aB = fma2(vb.x, h4.x, aB); aB = fma2(vb.y, h4.y, aB);
                }
                ull p = pack2(lo32(aA) + hi32(aA), lo32(aB) + hi32(aB));
                p = add2(p, __shfl_xor_sync(0xffffffffu, p, 8));
                p = add2(p, __shfl_xor_sync(0xffffffffu, p, 4));
                p = add2(p, __shfl_xor_sync(0xffffffffu, p, 2));
                p = add2(p, __shfl_xor_sync(0xffffffffu, p, 1));
                p = add2(p, bias2);

                float x0 = lo32(p), x1 = hi32(p);
                float s0 = fsig(g2 ? 2.0f * x0 : x0);
                float a0 = g2 ? (2.0f * s0 - 1.0f) : s0;
                float a1 = fsig(x1);
                float gi = __shfl_sync(0xffffffffu, a0, 0);
                float gf = __shfl_sync(0xffffffffu, a1, 0);
                float tg = __shfl_sync(0xffffffffu, a0, 16);
                float go = __shfl_sync(0xffffffffu, a1, 16);
                c2 = gf * c2 + gi * tg;
                float h = go * (2.0f * fsig(2.0f * c2) - 1.0f);
                if (l == 0) {
                    st_tag(g_tg2 + (size_t)s * NCLS + out2,
                           ((ull)(tb + (unsigned)s + 1u) << 32) | (ull)__float_as_uint(h));
                    outp[(size_t)s * NCLS + out2] = h;
                    if (s == SEQ - 1) g_cfin[2 * HID + out2] = c2;
                }
            }
        }
        pv = pvn;
    }
}

// ---------------- final output assembly ----------------
__global__ void finalize_kernel(float* __restrict__ out) {
    int i = blockIdx.x * blockDim.x + threadIdx.x;
    const int OB = SEQ * NCLS;   // 1048576: start of h_stack
    if (i < 1024)      out[OB + i] = g_hs0[(SEQ - 1) * HID + i];
    else if (i < 2048) out[OB + i] = g_hs1[(SEQ - 1) * HID + (i - 1024)];
    else if (i < 3072) out[OB + i] = g_cfin[i - 2048];                   // c0
    else if (i < 4096) out[OB + i] = g_cfin[HID + (i - 3072)];           // c1
    else if (i < 4352) out[OB + i] = out[(SEQ - 1) * NCLS + (i - 4096)]; // h2
    else if (i < 4608) out[OB + i] = g_cfin[2 * HID + (i - 4352)];       // c2
}

// ---------------- launch ----------------
extern "C" void kernel_launch(void* const* d_in, const int* in_sizes, int n_in,
                              void* d_out, int out_size)
{
    const int*   tokens = (const int*)  d_in[0];
    const float* embed  = (const float*)d_in[1];
    const float* w_ih0  = (const float*)d_in[2];
    const float* w_hh0  = (const float*)d_in[3];
    const float* b_ih0  = (const float*)d_in[4];
    const float* b_hh0  = (const float*)d_in[5];
    const float* w_ih1  = (const float*)d_in[6];
    const float* w_hh1  = (const float*)d_in[7];
    const float* b_ih1  = (const float*)d_in[8];
    const float* b_hh1  = (const float*)d_in[9];
    const float* w_ih2  = (const float*)d_in[10];
    const float* w_hh2  = (const float*)d_in[11];
    const float* b_ih2  = (const float*)d_in[12];
    const float* b_hh2  = (const float*)d_in[13];
    float* out = (float*)d_out;

    bump_gen_kernel<<<1, 32>>>();

    gemm_bias<0><<<dim3(4 * HID / 64, NCLS / 128), 256>>>(embed, w_ih0, b_ih0, b_hh0,
                                                          NCLS, 4 * HID, HID);
    lstm_scan0<<<HID / 8, 256>>>(w_hh0, tokens);

    gemm_bias<1><<<dim3(4 * HID / 64, SEQ / 128), 256>>>(nullptr, w_ih1, b_ih1, b_hh1,
                                                         SEQ, 4 * HID, HID);
    lstm_scan12<<<128, 320>>>(w_hh1, w_ih2, w_hh2, b_ih2, b_hh2, out);

    finalize_kernel<<<18, 256>>>(out);
}

// round 5
// speedup vs baseline: 1.2563x; 1.2563x over previous
#include <cuda_runtime.h>
#include <cstdint>

#define SEQ  4096
#define HID  1024
#define NCLS 256

typedef unsigned long long ull;

// ---------------- scratch (device globals) ----------------
__device__ float g_table[NCLS * 4 * HID];   //  4 MB  layer0 pre-activation table
__device__ float g_pre1 [SEQ  * 4 * HID];   // 64 MB  layer1 pre (GEMM output)
__device__ float g_hs0  [SEQ * HID];        // 16 MB  h0 (GEMM input)
__device__ float g_hs1  [SEQ * HID];        // 16 MB  h1 (finals)
__device__ ull   g_tg0  [SEQ * HID];        // 32 MB  tagged h0 handoff
__device__ ull   g_tg1  [SEQ * HID];        // 32 MB  tagged h1 handoff
__device__ ull   g_tg2  [SEQ * NCLS];       //  8 MB  tagged h2 handoff
__device__ float g_cfin [2 * HID + NCLS];   // c0, c1, c2 finals
__device__ unsigned int g_gen;

// ---------------- helpers ----------------
__device__ __forceinline__ float fsig(float x) {
    return __fdividef(1.0f, 1.0f + __expf(-x));
}
__device__ __forceinline__ float ftanh(float x) {
    float a = fabsf(x);
    float e = __expf(2.0f * a);
    float r = 1.0f - __fdividef(2.0f, e + 1.0f);
    return copysignf(r, x);
}
__device__ __forceinline__ ull ld_tag(const ull* p) {
    ull v;
    asm volatile("ld.relaxed.gpu.global.b64 %0, [%1];" : "=l"(v) : "l"(p) : "memory");
    return v;
}
__device__ __forceinline__ void st_tag(ull* p, ull v) {
    asm volatile("st.relaxed.gpu.global.b64 [%0], %1;" :: "l"(p), "l"(v) : "memory");
}
__device__ __forceinline__ ull fma2(ull a, ull b, ull c) {
    ull d;
    asm("fma.rn.f32x2 %0, %1, %2, %3;" : "=l"(d) : "l"(a), "l"(b), "l"(c));
    return d;
}
__device__ __forceinline__ float lo32(ull v) { return __uint_as_float((unsigned)v); }
__device__ __forceinline__ float hi32(ull v) { return __uint_as_float((unsigned)(v >> 32)); }

__global__ void bump_gen_kernel() { if (threadIdx.x == 0) g_gen += 1u; }

// batch-poll 4 tagged words until all carry tag
#define POLL4(src, i0, st, expect, d0, d1, d2, d3)                              \
    {                                                                           \
        ull _v0 = ld_tag((src) + (i0));                                         \
        ull _v1 = ld_tag((src) + (i0) + (st));                                  \
        ull _v2 = ld_tag((src) + (i0) + 2 * (st));                              \
        ull _v3 = ld_tag((src) + (i0) + 3 * (st));                              \
        while (!(((unsigned)(_v0 >> 32) == (expect)) &                          \
                 ((unsigned)(_v1 >> 32) == (expect)) &                          \
                 ((unsigned)(_v2 >> 32) == (expect)) &                          \
                 ((unsigned)(_v3 >> 32) == (expect)))) {                        \
            _v0 = ld_tag((src) + (i0));                                         \
            _v1 = ld_tag((src) + (i0) + (st));                                  \
            _v2 = ld_tag((src) + (i0) + 2 * (st));                              \
            _v3 = ld_tag((src) + (i0) + 3 * (st));                              \
        }                                                                       \
        d0 = __uint_as_float((unsigned)_v0);                                    \
        d1 = __uint_as_float((unsigned)_v1);                                    \
        d2 = __uint_as_float((unsigned)_v2);                                    \
        d3 = __uint_as_float((unsigned)_v3);                                    \
    }

// ---------------- GEMM:  C[M][N] = A[M][K] @ B[N][K]^T + b1[N] + b2[N] -----
template<int WHICH>
__global__ void __launch_bounds__(256)
gemm_bias(const float* __restrict__ Ain, const float* __restrict__ B,
          const float* __restrict__ b1, const float* __restrict__ b2,
          int M, int N, int K)
{
    const float* A = (WHICH == 1) ? g_hs0 : Ain;
    float*       C = (WHICH == 0) ? g_table : g_pre1;

    __shared__ float As[16][136];
    __shared__ float Bs[16][72];

    const int m0 = blockIdx.y * 128;
    const int n0 = blockIdx.x * 64;
    const int tid = threadIdx.x;
    const int tm = tid >> 4;
    const int tn = tid & 15;
    const int lra = tid >> 1;
    const int lka = (tid & 1) * 8;
    const int lrb = tid >> 2;
    const int lkb = (tid & 3) * 4;

    float acc[8][4];
#pragma unroll
    for (int i = 0; i < 8; i++)
#pragma unroll
        for (int j = 0; j < 4; j++) acc[i][j] = 0.0f;

    for (int kt = 0; kt < K; kt += 16) {
        float4 a0 = *reinterpret_cast<const float4*>(&A[(size_t)(m0 + lra) * K + kt + lka]);
        float4 a1 = *reinterpret_cast<const float4*>(&A[(size_t)(m0 + lra) * K + kt + lka + 4]);
        float4 bv = *reinterpret_cast<const float4*>(&B[(size_t)(n0 + lrb) * K + kt + lkb]);
        __syncthreads();
        As[lka + 0][lra] = a0.x; As[lka + 1][lra] = a0.y; As[lka + 2][lra] = a0.z; As[lka + 3][lra] = a0.w;
        As[lka + 4][lra] = a1.x; As[lka + 5][lra] = a1.y; As[lka + 6][lra] = a1.z; As[lka + 7][lra] = a1.w;
        Bs[lkb + 0][lrb] = bv.x; Bs[lkb + 1][lrb] = bv.y; Bs[lkb + 2][lrb] = bv.z; Bs[lkb + 3][lrb] = bv.w;
        __syncthreads();
#pragma unroll
        for (int kk = 0; kk < 16; kk++) {
            float4 a4 = *reinterpret_cast<const float4*>(&As[kk][tm * 8]);
            float4 a5 = *reinterpret_cast<const float4*>(&As[kk][tm * 8 + 4]);
            float4 b4 = *reinterpret_cast<const float4*>(&Bs[kk][tn * 4]);
            float a[8] = {a4.x, a4.y, a4.z, a4.w, a5.x, a5.y, a5.z, a5.w};
            float b[4] = {b4.x, b4.y, b4.z, b4.w};
#pragma unroll
            for (int i = 0; i < 8; i++)
#pragma unroll
                for (int j = 0; j < 4; j++) acc[i][j] += a[i] * b[j];
        }
    }

    const int col0 = n0 + tn * 4;
    float4 v1 = *reinterpret_cast<const float4*>(&b1[col0]);
    float4 v2 = *reinterpret_cast<const float4*>(&b2[col0]);
    float bias[4] = {v1.x + v2.x, v1.y + v2.y, v1.z + v2.z, v1.w + v2.w};
#pragma unroll
    for (int i = 0; i < 8; i++) {
        int row = m0 + tm * 8 + i;
        float4 o;
        o.x = acc[i][0] + bias[0];
        o.y = acc[i][1] + bias[1];
        o.z = acc[i][2] + bias[2];
        o.w = acc[i][3] + bias[3];
        *reinterpret_cast<float4*>(&C[(size_t)row * N + col0]) = o;
    }
}

// ---------------- layer-0 scan (R3-proven structure) ----------------
__global__ void __launch_bounds__(256, 1)
lstm_scan0(const float* __restrict__ whh, const int* __restrict__ tokens)
{
    const int tid = threadIdx.x;
    const int w = tid >> 5;
    const int l = tid & 31;
    const int out = blockIdx.x * 8 + w;
    const unsigned tb = g_gen * (unsigned)(SEQ + 1);

    __shared__ __align__(16) float sh[2][HID];
    __shared__ int stok[SEQ];

    ulonglong2 wq[4][8];
#pragma unroll
    for (int r = 0; r < 4; r++)
#pragma unroll
        for (int i = 0; i < 8; i++)
            wq[r][i] = *reinterpret_cast<const ulonglong2*>(
                whh + (size_t)(r * HID + out) * HID + i * 128 + 4 * l);

    for (int i = tid; i < SEQ; i += 256) stok[i] = tokens[i];
    for (int i = tid; i < HID; i += 256) sh[0][i] = 0.0f;
    __syncthreads();

    auto loadpre = [&](int tt, int r) -> float {
        return __ldg(&g_table[(size_t)stok[tt] * (4 * HID) + r * HID + out]);
    };

    float c = 0.0f;
    float pv = (l < 4) ? loadpre(0, l) : 0.0f;

    for (int t = 0; t < SEQ; t++) {
        float pvn = (l < 4 && t + 1 < SEQ) ? loadpre(t + 1, l) : 0.0f;

        float* shb = sh[t & 1];
        if (t > 0) {
            const ull* src = g_tg0 + (size_t)(t - 1) * HID;
            const unsigned expect = tb + (unsigned)t;
            float d0, d1, d2, d3;
            POLL4(src, tid, 256, expect, d0, d1, d2, d3);
            shb[tid] = d0; shb[tid + 256] = d1; shb[tid + 512] = d2; shb[tid + 768] = d3;
        }
        __syncthreads();

        ull acc[4] = {0ull, 0ull, 0ull, 0ull};
#pragma unroll
        for (int i = 0; i < 8; i++) {
            ulonglong2 hv = *reinterpret_cast<const ulonglong2*>(shb + i * 128 + 4 * l);
#pragma unroll
            for (int r = 0; r < 4; r++) {
                acc[r] = fma2(wq[r][i].x, hv.x, acc[r]);
                acc[r] = fma2(wq[r][i].y, hv.y, acc[r]);
            }
        }
        float g[4];
#pragma unroll
        for (int r = 0; r < 4; r++) g[r] = lo32(acc[r]) + hi32(acc[r]);
#pragma unroll
        for (int s = 16; s > 0; s >>= 1)
#pragma unroll
            for (int r = 0; r < 4; r++) g[r] += __shfl_xor_sync(0xffffffffu, g[r], s);

        const float p0 = __shfl_sync(0xffffffffu, pv, 0);
        const float p1 = __shfl_sync(0xffffffffu, pv, 1);
        const float p2 = __shfl_sync(0xffffffffu, pv, 2);
        const float p3 = __shfl_sync(0xffffffffu, pv, 3);

        c = fsig(g[1] + p1) * c + fsig(g[0] + p0) * ftanh(g[2] + p2);
        const float h = fsig(g[3] + p3) * ftanh(c);

        if (l == 0) {
            st_tag(g_tg0 + (size_t)t * HID + out,
                   ((ull)(tb + (unsigned)t + 1u) << 32) | (ull)__float_as_uint(h));
            g_hs0[(size_t)t * HID + out] = h;
            if (t == SEQ - 1) g_cfin[out] = c;
        }
        pv = pvn;
    }
}

// ---------------- fused layer1 + layer2 scan: 128 CTAs x 320 thr ----------
// warps 0-7 (tid<256): layer1, identical to R3 scan but bar.sync 1,256.
// warps 8-9 (64 thr):  layer2, 2 outputs/CTA, fully decoupled (bar.sync 2,64),
// polls g_tg1 (lag 1 step -> usually ready) + g_tg2 (own 256-wide recurrence).
__global__ void __launch_bounds__(320, 1)
lstm_scan12(const float* __restrict__ whh1, const float* __restrict__ wih2,
            const float* __restrict__ whh2, const float* __restrict__ bih2,
            const float* __restrict__ bhh2, float* __restrict__ outp)
{
    const int tid = threadIdx.x;
    const int w = tid >> 5;
    const int l = tid & 31;
    const unsigned tb = g_gen * (unsigned)(SEQ + 1);
    const bool isL1 = (w < 8);
    const int out  = blockIdx.x * 8 + w;        // L1 output id
    const int oo   = w - 8;                      // local L2 output (0/1)
    const int out2 = blockIdx.x * 2 + oo;        // L2 output id

    __shared__ __align__(16) float sh [2][HID];   // L1 h1_{t-1} staging
    __shared__ __align__(16) float s1x[2][HID];   // L2 h1_t staging
    __shared__ __align__(16) float s2x[2][NCLS];  // L2 h2_{t-1} staging
    __shared__ __align__(16) float whs[2][4][NCLS];

    // weights: L1 -> w_hh1; L2 -> w_ih2. Both 4 rows x 32 floats/lane, k=4l+128i.
    ulonglong2 wq[4][8];
    if (isL1) {
#pragma unroll
        for (int r = 0; r < 4; r++)
#pragma unroll
            for (int i = 0; i < 8; i++)
                wq[r][i] = *reinterpret_cast<const ulonglong2*>(
                    whh1 + (size_t)(r * HID + out) * HID + i * 128 + 4 * l);
    } else {
#pragma unroll
        for (int r = 0; r < 4; r++)
#pragma unroll
            for (int i = 0; i < 8; i++)
                wq[r][i] = *reinterpret_cast<const ulonglong2*>(
                    wih2 + (size_t)(r * NCLS + out2) * HID + i * 128 + 4 * l);
    }

    // w_hh2 slices into SMEM (2 outputs x 4 gates x 256)
    for (int i = tid; i < 2 * 4 * NCLS; i += 320) {
        int o = i >> 10, rem = i & 1023, r = rem >> 8, k = rem & 255;
        whs[o][r][k] = whh2[(size_t)(r * NCLS + blockIdx.x * 2 + o) * NCLS + k];
    }
    for (int i = tid; i < 2 * HID; i += 320)  ((float*)sh)[i] = 0.0f;
    for (int i = tid; i < 2 * NCLS; i += 320) ((float*)s2x)[i] = 0.0f;
    __syncthreads();   // only sync joining both groups (init)

    if (isL1) {
        // ================= LAYER 1 (identical critical path to R3) =========
        auto loadpre = [&](int tt, int r) -> float {
            return __ldg(&g_pre1[(size_t)tt * (4 * HID) + r * HID + out]);
        };
        float c = 0.0f;
        float pv = (l < 4) ? loadpre(0, l) : 0.0f;

        for (int t = 0; t < SEQ; t++) {
            float pvn = (l < 4 && t + 1 < SEQ) ? loadpre(t + 1, l) : 0.0f;

            float* shb = sh[t & 1];
            if (t > 0) {
                const ull* src = g_tg1 + (size_t)(t - 1) * HID;
                const unsigned expect = tb + (unsigned)t;
                float d0, d1, d2, d3;
                POLL4(src, tid, 256, expect, d0, d1, d2, d3);
                shb[tid] = d0; shb[tid + 256] = d1; shb[tid + 512] = d2; shb[tid + 768] = d3;
            }
            asm volatile("bar.sync 1, 256;" ::: "memory");

            ull acc[4] = {0ull, 0ull, 0ull, 0ull};
#pragma unroll
            for (int i = 0; i < 8; i++) {
                ulonglong2 hv = *reinterpret_cast<const ulonglong2*>(shb + i * 128 + 4 * l);
#pragma unroll
                for (int r = 0; r < 4; r++) {
                    acc[r] = fma2(wq[r][i].x, hv.x, acc[r]);
                    acc[r] = fma2(wq[r][i].y, hv.y, acc[r]);
                }
            }
            float g[4];
#pragma unroll
            for (int r = 0; r < 4; r++) g[r] = lo32(acc[r]) + hi32(acc[r]);
#pragma unroll
            for (int s = 16; s > 0; s >>= 1)
#pragma unroll
                for (int r = 0; r < 4; r++) g[r] += __shfl_xor_sync(0xffffffffu, g[r], s);

            const float p0 = __shfl_sync(0xffffffffu, pv, 0);
            const float p1 = __shfl_sync(0xffffffffu, pv, 1);
            const float p2 = __shfl_sync(0xffffffffu, pv, 2);
            const float p3 = __shfl_sync(0xffffffffu, pv, 3);

            c = fsig(g[1] + p1) * c + fsig(g[0] + p0) * ftanh(g[2] + p2);
            const float h = fsig(g[3] + p3) * ftanh(c);

            if (l == 0) {
                st_tag(g_tg1 + (size_t)t * HID + out,
                       ((ull)(tb + (unsigned)t + 1u) << 32) | (ull)__float_as_uint(h));
                g_hs1[(size_t)t * HID + out] = h;
                if (t == SEQ - 1) g_cfin[HID + out] = c;
            }
            pv = pvn;
        }
    } else {
        // ================= LAYER 2 (2 warps, own barrier) ===================
        const int t2 = tid - 256;                  // 0..63
        float bias = 0.0f;
        if (l < 4) bias = bih2[l * NCLS + out2] + bhh2[l * NCLS + out2];

        float c = 0.0f;
        for (int t = 0; t < SEQ; t++) {
            // stage h1_t (tag tb+t+1) and h2_{t-1} (tag tb+t), all loads in flight
            {
                const ull* src1 = g_tg1 + (size_t)t * HID;
                const unsigned e1 = tb + (unsigned)t + 1u;
                ull v[16];
#pragma unroll
                for (int m = 0; m < 16; m++) v[m] = ld_tag(src1 + t2 + 64 * m);
                if (t > 0) {
                    const ull* src2 = g_tg2 + (size_t)(t - 1) * NCLS;
                    const unsigned e2 = tb + (unsigned)t;
                    ull u[4];
#pragma unroll
                    for (int m = 0; m < 4; m++) u[m] = ld_tag(src2 + t2 + 64 * m);
                    while (true) {
                        bool ok = true;
#pragma unroll
                        for (int m = 0; m < 16; m++) ok &= ((unsigned)(v[m] >> 32) == e1);
#pragma unroll
                        for (int m = 0; m < 4; m++)  ok &= ((unsigned)(u[m] >> 32) == e2);
                        if (ok) break;
#pragma unroll
                        for (int m = 0; m < 16; m++) v[m] = ld_tag(src1 + t2 + 64 * m);
#pragma unroll
                        for (int m = 0; m < 4; m++)  u[m] = ld_tag(src2 + t2 + 64 * m);
                    }
                    float* s2 = s2x[t & 1];
#pragma unroll
                    for (int m = 0; m < 4; m++)
                        s2[t2 + 64 * m] = __uint_as_float((unsigned)u[m]);
                } else {
                    while (true) {
                        bool ok = true;
#pragma unroll
                        for (int m = 0; m < 16; m++) ok &= ((unsigned)(v[m] >> 32) == e1);
                        if (ok) break;
#pragma unroll
                        for (int m = 0; m < 16; m++) v[m] = ld_tag(src1 + t2 + 64 * m);
                    }
                }
                float* s1 = s1x[t & 1];
#pragma unroll
                for (int m = 0; m < 16; m++)
                    s1[t2 + 64 * m] = __uint_as_float((unsigned)v[m]);
            }
            asm volatile("bar.sync 2, 64;" ::: "memory");

            const float* s1 = s1x[t & 1];
            const float* s2 = s2x[t & 1];
            ull acc[4] = {0ull, 0ull, 0ull, 0ull};
#pragma unroll
            for (int i = 0; i < 8; i++) {
                ulonglong2 hv = *reinterpret_cast<const ulonglong2*>(s1 + i * 128 + 4 * l);
#pragma unroll
                for (int r = 0; r < 4; r++) {
                    acc[r] = fma2(wq[r][i].x, hv.x, acc[r]);
                    acc[r] = fma2(wq[r][i].y, hv.y, acc[r]);
                }
            }
            // h2 recurrence: k = 4l + 128i, i=0..1; weights from SMEM
#pragma unroll
            for (int i = 0; i < 2; i++) {
                ulonglong2 hv = *reinterpret_cast<const ulonglong2*>(s2 + i * 128 + 4 * l);
#pragma unroll
                for (int r = 0; r < 4; r++) {
                    ulonglong2 wv = *reinterpret_cast<const ulonglong2*>(&whs[oo][r][i * 128 + 4 * l]);
                    acc[r] = fma2(wv.x, hv.x, acc[r]);
                    acc[r] = fma2(wv.y, hv.y, acc[r]);
                }
            }
            float g[4];
#pragma unroll
            for (int r = 0; r < 4; r++) g[r] = lo32(acc[r]) + hi32(acc[r]);
#pragma unroll
            for (int s = 16; s > 0; s >>= 1)
#pragma unroll
                for (int r = 0; r < 4; r++) g[r] += __shfl_xor_sync(0xffffffffu, g[r], s);

            const float p0 = __shfl_sync(0xffffffffu, bias, 0);
            const float p1 = __shfl_sync(0xffffffffu, bias, 1);
            const float p2 = __shfl_sync(0xffffffffu, bias, 2);
            const float p3 = __shfl_sync(0xffffffffu, bias, 3);

            c = fsig(g[1] + p1) * c + fsig(g[0] + p0) * ftanh(g[2] + p2);
            const float h = fsig(g[3] + p3) * ftanh(c);

            if (l == 0) {
                st_tag(g_tg2 + (size_t)t * NCLS + out2,
                       ((ull)(tb + (unsigned)t + 1u) << 32) | (ull)__float_as_uint(h));
                outp[(size_t)t * NCLS + out2] = h;
                if (t == SEQ - 1) g_cfin[2 * HID + out2] = c;
            }
        }
    }
}

// ---------------- final output assembly ----------------
__global__ void finalize_kernel(float* __restrict__ out) {
    int i = blockIdx.x * blockDim.x + threadIdx.x;
    const int OB = SEQ * NCLS;
    if (i < 1024)      out[OB + i] = g_hs0[(SEQ - 1) * HID + i];
    else if (i < 2048) out[OB + i] = g_hs1[(SEQ - 1) * HID + (i - 1024)];
    else if (i < 3072) out[OB + i] = g_cfin[i - 2048];                   // c0
    else if (i < 4096) out[OB + i] = g_cfin[HID + (i - 3072)];           // c1
    else if (i < 4352) out[OB + i] = out[(SEQ - 1) * NCLS + (i - 4096)]; // h2
    else if (i < 4608) out[OB + i] = g_cfin[2 * HID + (i - 4352)];       // c2
}

// ---------------- launch ----------------
extern "C" void kernel_launch(void* const* d_in, const int* in_sizes, int n_in,
                              void* d_out, int out_size)
{
    const int*   tokens = (const int*)  d_in[0];
    const float* embed  = (const float*)d_in[1];
    const float* w_ih0  = (const float*)d_in[2];
    const float* w_hh0  = (const float*)d_in[3];
    const float* b_ih0  = (const float*)d_in[4];
    const float* b_hh0  = (const float*)d_in[5];
    const float* w_ih1  = (const float*)d_in[6];
    const float* w_hh1  = (const float*)d_in[7];
    const float* b_ih1  = (const float*)d_in[8];
    const float* b_hh1  = (const float*)d_in[9];
    const float* w_ih2  = (const float*)d_in[10];
    const float* w_hh2  = (const float*)d_in[11];
    const float* b_ih2  = (const float*)d_in[12];
    const float* b_hh2  = (const float*)d_in[13];
    float* out = (float*)d_out;

    bump_gen_kernel<<<1, 32>>>();

    gemm_bias<0><<<dim3(4 * HID / 64, NCLS / 128), 256>>>(embed, w_ih0, b_ih0, b_hh0,
                                                          NCLS, 4 * HID, HID);
    lstm_scan0<<<HID / 8, 256>>>(w_hh0, tokens);

    gemm_bias<1><<<dim3(4 * HID / 64, SEQ / 128), 256>>>(nullptr, w_ih1, b_ih1, b_hh1,
                                                         SEQ, 4 * HID, HID);
    lstm_scan12<<<128, 320>>>(w_hh1, w_ih2, w_hh2, b_ih2, b_hh2, out);

    finalize_kernel<<<18, 256>>>(out);
}

// round 8
// speedup vs baseline: 1.6160x; 1.2863x over previous
#include <cuda_runtime.h>
#include <cstdint>

#define SEQ  4096
#define HID  1024
#define NCLS 256

typedef unsigned long long ull;

// ---------------- scratch (device globals) ----------------
__device__ float g_table[NCLS * 4 * HID];   //  4 MB  layer0 pre-activation table
__device__ float g_pre1 [SEQ  * 4 * HID];   // 64 MB  layer1 pre
__device__ float g_pre2 [SEQ  * 4 * NCLS];  // 16 MB  layer2 pre
__device__ float g_hs0  [SEQ * HID];        // 16 MB  h0 (GEMM input)
__device__ float g_hs1  [SEQ * HID];        // 16 MB  h1 (GEMM input / finals)
__device__ ull   g_tg0  [SEQ * HID];        // 32 MB  tagged h0 handoff
__device__ ull   g_tg1  [SEQ * HID];        // 32 MB  tagged h1 handoff
__device__ ull   g_tg2  [SEQ * NCLS];       //  8 MB  tagged h2 handoff
__device__ float g_cfin [2 * HID + NCLS];   // c0, c1, c2 finals
__device__ unsigned int g_gen;

// ---------------- helpers ----------------
__device__ __forceinline__ float fsig(float x) {
    return __fdividef(1.0f, 1.0f + __expf(-x));
}
// exact-path tanh: 2/(1+e^-2x) - 1 ; saturates correctly at +-inf args
__device__ __forceinline__ float ftanh(float x) {
    return __fdividef(2.0f, 1.0f + __expf(-2.0f * x)) - 1.0f;
}
__device__ __forceinline__ ull ld_tag(const ull* p) {
    ull v;
    asm volatile("ld.relaxed.gpu.global.b64 %0, [%1];" : "=l"(v) : "l"(p) : "memory");
    return v;
}
__device__ __forceinline__ void st_tag(ull* p, ull v) {
    asm volatile("st.relaxed.gpu.global.b64 [%0], %1;" :: "l"(p), "l"(v) : "memory");
}
__device__ __forceinline__ ull fma2(ull a, ull b, ull c) {
    ull d;
    asm("fma.rn.f32x2 %0, %1, %2, %3;" : "=l"(d) : "l"(a), "l"(b), "l"(c));
    return d;
}
__device__ __forceinline__ ull add2(ull a, ull b) {
    ull d;
    asm("add.rn.f32x2 %0, %1, %2;" : "=l"(d) : "l"(a), "l"(b));
    return d;
}
__device__ __forceinline__ ull pack2(float lo, float hi) {
    ull d;
    asm("mov.b64 %0, {%1, %2};" : "=l"(d) : "f"(lo), "f"(hi));
    return d;
}
__device__ __forceinline__ float lo32(ull v) { return __uint_as_float((unsigned)v); }
__device__ __forceinline__ float hi32(ull v) { return __uint_as_float((unsigned)(v >> 32)); }

__global__ void bump_gen_kernel() { if (threadIdx.x == 0) g_gen += 1u; }

// batch-poll 4 tagged words; retry reloads ONLY stale words (cuts poll bytes)
#define POLL4(src, i0, st, expect, d0, d1, d2, d3)                              \
    {                                                                           \
        ull _v0 = ld_tag((src) + (i0));                                         \
        ull _v1 = ld_tag((src) + (i0) + (st));                                  \
        ull _v2 = ld_tag((src) + (i0) + 2 * (st));                              \
        ull _v3 = ld_tag((src) + (i0) + 3 * (st));                              \
        while (true) {                                                          \
            bool _o0 = ((unsigned)(_v0 >> 32) == (expect));                     \
            bool _o1 = ((unsigned)(_v1 >> 32) == (expect));                     \
            bool _o2 = ((unsigned)(_v2 >> 32) == (expect));                     \
            bool _o3 = ((unsigned)(_v3 >> 32) == (expect));                     \
            if (_o0 & _o1 & _o2 & _o3) break;                                   \
            if (!_o0) _v0 = ld_tag((src) + (i0));                               \
            if (!_o1) _v1 = ld_tag((src) + (i0) + (st));                        \
            if (!_o2) _v2 = ld_tag((src) + (i0) + 2 * (st));                    \
            if (!_o3) _v3 = ld_tag((src) + (i0) + 3 * (st));                    \
        }                                                                       \
        d0 = __uint_as_float((unsigned)_v0);                                    \
        d1 = __uint_as_float((unsigned)_v1);                                    \
        d2 = __uint_as_float((unsigned)_v2);                                    \
        d3 = __uint_as_float((unsigned)_v3);                                    \
    }

// ---------------- GEMM:  C[M][N] = A[M][K] @ B[N][K]^T + b1[N] + b2[N] -----
template<int WHICH>
__global__ void __launch_bounds__(256)
gemm_bias(const float* __restrict__ Ain, const float* __restrict__ B,
          const float* __restrict__ b1, const float* __restrict__ b2,
          int M, int N, int K)
{
    const float* A = (WHICH == 1) ? g_hs0 : (WHICH == 2) ? g_hs1 : Ain;
    float*       C = (WHICH == 0) ? g_table : (WHICH == 1) ? g_pre1 : g_pre2;

    __shared__ float As[16][136];
    __shared__ float Bs[16][72];

    const int m0 = blockIdx.y * 128;
    const int n0 = blockIdx.x * 64;
    const int tid = threadIdx.x;
    const int tm = tid >> 4;
    const int tn = tid & 15;
    const int lra = tid >> 1;
    const int lka = (tid & 1) * 8;
    const int lrb = tid >> 2;
    const int lkb = (tid & 3) * 4;

    float acc[8][4];
#pragma unroll
    for (int i = 0; i < 8; i++)
#pragma unroll
        for (int j = 0; j < 4; j++) acc[i][j] = 0.0f;

    for (int kt = 0; kt < K; kt += 16) {
        float4 a0 = *reinterpret_cast<const float4*>(&A[(size_t)(m0 + lra) * K + kt + lka]);
        float4 a1 = *reinterpret_cast<const float4*>(&A[(size_t)(m0 + lra) * K + kt + lka + 4]);
        float4 bv = *reinterpret_cast<const float4*>(&B[(size_t)(n0 + lrb) * K + kt + lkb]);
        __syncthreads();
        As[lka + 0][lra] = a0.x; As[lka + 1][lra] = a0.y; As[lka + 2][lra] = a0.z; As[lka + 3][lra] = a0.w;
        As[lka + 4][lra] = a1.x; As[lka + 5][lra] = a1.y; As[lka + 6][lra] = a1.z; As[lka + 7][lra] = a1.w;
        Bs[lkb + 0][lrb] = bv.x; Bs[lkb + 1][lrb] = bv.y; Bs[lkb + 2][lrb] = bv.z; Bs[lkb + 3][lrb] = bv.w;
        __syncthreads();
#pragma unroll
        for (int kk = 0; kk < 16; kk++) {
            float4 a4 = *reinterpret_cast<const float4*>(&As[kk][tm * 8]);
            float4 a5 = *reinterpret_cast<const float4*>(&As[kk][tm * 8 + 4]);
            float4 b4 = *reinterpret_cast<const float4*>(&Bs[kk][tn * 4]);
            float a[8] = {a4.x, a4.y, a4.z, a4.w, a5.x, a5.y, a5.z, a5.w};
            float b[4] = {b4.x, b4.y, b4.z, b4.w};
#pragma unroll
            for (int i = 0; i < 8; i++)
#pragma unroll
                for (int j = 0; j < 4; j++) acc[i][j] += a[i] * b[j];
        }
    }

    const int col0 = n0 + tn * 4;
    float4 v1 = *reinterpret_cast<const float4*>(&b1[col0]);
    float4 v2 = *reinterpret_cast<const float4*>(&b2[col0]);
    float bias[4] = {v1.x + v2.x, v1.y + v2.y, v1.z + v2.z, v1.w + v2.w};
#pragma unroll
    for (int i = 0; i < 8; i++) {
        int row = m0 + tm * 8 + i;
        float4 o;
        o.x = acc[i][0] + bias[0];
        o.y = acc[i][1] + bias[1];
        o.z = acc[i][2] + bias[2];
        o.w = acc[i][3] + bias[3];
        *reinterpret_cast<float4*>(&C[(size_t)row * N + col0]) = o;
    }
}

// ---------------- LSTM scan (warp-per-output, tagged handoff) ----------------
// 8 warps/CTA, warp w owns output (cta*8+w) = 4 gate rows; weights in regs.
// Packed-f32x2 butterfly reduction (broadcast), all-lane epilogue, no gathers.
template<int INDIM, int OUTDIM, int LAYER>
__global__ void __launch_bounds__(256, 1)
lstm_scan(const float* __restrict__ whh,       // [4*OUTDIM][INDIM]
          const int*   __restrict__ tokens,    // layer 0 only
          float*       __restrict__ hs_param)  // layer 2: d_out
{
    constexpr int KITER = INDIM / 128;   // 8 (HID) or 2 (NCLS)
    constexpr int PPT   = INDIM / 256;   // 4 (HID) or 1 (NCLS)

    const float* pre = (LAYER == 0) ? g_table : (LAYER == 1) ? g_pre1 : g_pre2;
    ull*   tg = (LAYER == 0) ? g_tg0 : (LAYER == 1) ? g_tg1 : g_tg2;
    float* hs = (LAYER == 0) ? g_hs0 : (LAYER == 1) ? g_hs1 : hs_param;
    float* cf = g_cfin + ((LAYER == 0) ? 0 : (LAYER == 1) ? HID : 2 * HID);

    const int tid = threadIdx.x;
    const int w = tid >> 5;
    const int l = tid & 31;
    const int out = blockIdx.x * 8 + w;
    const unsigned tb = g_gen * (unsigned)(SEQ + 1);

    __shared__ __align__(16) float sh[2][INDIM];
    __shared__ int stok[(LAYER == 0) ? SEQ : 1];

    // register-resident weights: 4 gate rows, this lane's k-slices
    ulonglong2 wq[4][KITER];
#pragma unroll
    for (int r = 0; r < 4; r++)
#pragma unroll
        for (int i = 0; i < KITER; i++)
            wq[r][i] = *reinterpret_cast<const ulonglong2*>(
                whh + (size_t)(r * OUTDIM + out) * INDIM + i * 128 + 4 * l);

    if constexpr (LAYER == 0) {
        for (int i = tid; i < SEQ; i += 256) stok[i] = tokens[i];
    }
    for (int i = tid; i < INDIM; i += 256) sh[0][i] = 0.0f;
    __syncthreads();

    // all lanes load all 4 gate pre values (warp-broadcast LDGs, no shfl later)
    auto loadpre = [&](int tt, float* p4) {
        size_t base;
        if constexpr (LAYER == 0) base = (size_t)stok[tt] * (4 * OUTDIM);
        else                      base = (size_t)tt * (4 * OUTDIM);
#pragma unroll
        for (int r = 0; r < 4; r++) p4[r] = __ldg(&pre[base + r * OUTDIM + out]);
    };

    float c = 0.0f;
    float pv[4];
    loadpre(0, pv);

    for (int t = 0; t < SEQ; t++) {
        float pvn[4] = {0.f, 0.f, 0.f, 0.f};
        if (t + 1 < SEQ) loadpre(t + 1, pvn);

        float* shb = sh[t & 1];
        if (t > 0) {
            const ull* src = tg + (size_t)(t - 1) * INDIM;
            const unsigned expect = tb + (unsigned)t;
            if constexpr (PPT == 4) {
                // layers 0/1: 256 threads x 4 words, stride 256 (in-bounds: 1024)
                float d0, d1, d2, d3;
                POLL4(src, tid, 256, expect, d0, d1, d2, d3);
                shb[tid] = d0; shb[tid + 256] = d1; shb[tid + 512] = d2; shb[tid + 768] = d3;
            } else {
                // layer 2: row is 256 words -> only 64 threads, stride 64
                if (tid < 64) {
                    float d0, d1, d2, d3;
                    POLL4(src, tid, 64, expect, d0, d1, d2, d3);
                    shb[tid] = d0; shb[tid + 64] = d1; shb[tid + 128] = d2; shb[tid + 192] = d3;
                }
            }
        }
        __syncthreads();

        // 4 gate-row dot products, packed f32x2 FMA
        ull acc[4] = {0ull, 0ull, 0ull, 0ull};
#pragma unroll
        for (int i = 0; i < KITER; i++) {
            ulonglong2 hv = *reinterpret_cast<const ulonglong2*>(shb + i * 128 + 4 * l);
#pragma unroll
            for (int r = 0; r < 4; r++) {
                acc[r] = fma2(wq[r][i].x, hv.x, acc[r]);
                acc[r] = fma2(wq[r][i].y, hv.y, acc[r]);
            }
        }
        // packed butterfly: both ulls pipelined per stage; all lanes end with sums
        ull p01 = pack2(lo32(acc[0]) + hi32(acc[0]), lo32(acc[1]) + hi32(acc[1]));
        ull p23 = pack2(lo32(acc[2]) + hi32(acc[2]), lo32(acc[3]) + hi32(acc[3]));
#pragma unroll
        for (int s = 16; s > 0; s >>= 1) {
            p01 = add2(p01, __shfl_xor_sync(0xffffffffu, p01, s));
            p23 = add2(p23, __shfl_xor_sync(0xffffffffu, p23, s));
        }
        const float s0 = lo32(p01) + pv[0];
        const float s1 = hi32(p01) + pv[1];
        const float s2 = lo32(p23) + pv[2];
        const float s3 = hi32(p23) + pv[3];

        // all lanes compute identical epilogue (no shfl, no divergence)
        c = fsig(s1) * c + fsig(s0) * ftanh(s2);
        const float h = fsig(s3) * ftanh(c);

        if (l == 0) {
            st_tag(tg + (size_t)t * OUTDIM + out,
                   ((ull)(tb + (unsigned)t + 1u) << 32) | (ull)__float_as_uint(h));
            hs[(size_t)t * OUTDIM + out] = h;
            if (t == SEQ - 1) cf[out] = c;
        }
#pragma unroll
        for (int r = 0; r < 4; r++) pv[r] = pvn[r];
    }
}

// ---------------- final output assembly ----------------
__global__ void finalize_kernel(float* __restrict__ out) {
    int i = blockIdx.x * blockDim.x + threadIdx.x;
    const int OB = SEQ * NCLS;   // 1048576: start of h_stack
    if (i < 1024)      out[OB + i] = g_hs0[(SEQ - 1) * HID + i];
    else if (i < 2048) out[OB + i] = g_hs1[(SEQ - 1) * HID + (i - 1024)];
    else if (i < 3072) out[OB + i] = g_cfin[i - 2048];                   // c0
    else if (i < 4096) out[OB + i] = g_cfin[HID + (i - 3072)];           // c1
    else if (i < 4352) out[OB + i] = out[(SEQ - 1) * NCLS + (i - 4096)]; // h2
    else if (i < 4608) out[OB + i] = g_cfin[2 * HID + (i - 4352)];       // c2
}

// ---------------- launch ----------------
extern "C" void kernel_launch(void* const* d_in, const int* in_sizes, int n_in,
                              void* d_out, int out_size)
{
    const int*   tokens = (const int*)  d_in[0];
    const float* embed  = (const float*)d_in[1];
    const float* w_ih0  = (const float*)d_in[2];
    const float* w_hh0  = (const float*)d_in[3];
    const float* b_ih0  = (const float*)d_in[4];
    const float* b_hh0  = (const float*)d_in[5];
    const float* w_ih1  = (const float*)d_in[6];
    const float* w_hh1  = (const float*)d_in[7];
    const float* b_ih1  = (const float*)d_in[8];
    const float* b_hh1  = (const float*)d_in[9];
    const float* w_ih2  = (const float*)d_in[10];
    const float* w_hh2  = (const float*)d_in[11];
    const float* b_ih2  = (const float*)d_in[12];
    const float* b_hh2  = (const float*)d_in[13];
    float* out = (float*)d_out;

    bump_gen_kernel<<<1, 32>>>();

    gemm_bias<0><<<dim3(4 * HID / 64, NCLS / 128), 256>>>(embed, w_ih0, b_ih0, b_hh0,
                                                          NCLS, 4 * HID, HID);
    lstm_scan<HID, HID, 0><<<HID / 8, 256>>>(w_hh0, tokens, nullptr);

    gemm_bias<1><<<dim3(4 * HID / 64, SEQ / 128), 256>>>(nullptr, w_ih1, b_ih1, b_hh1,
                                                         SEQ, 4 * HID, HID);
    lstm_scan<HID, HID, 1><<<HID / 8, 256>>>(w_hh1, nullptr, nullptr);

    gemm_bias<2><<<dim3(4 * NCLS / 64, SEQ / 128), 256>>>(nullptr, w_ih2, b_ih2, b_hh2,
                                                          SEQ, 4 * NCLS, HID);
    lstm_scan<NCLS, NCLS, 2><<<NCLS / 8, 256>>>(w_hh2, nullptr, out);

    finalize_kernel<<<18, 256>>>(out);
}

// round 9
// speedup vs baseline: 1.7873x; 1.1060x over previous
#include <cuda_runtime.h>
#include <cstdint>

#define SEQ  4096
#define HID  1024
#define NCLS 256

typedef unsigned long long ull;

// ---------------- scratch (device globals) ----------------
__device__ float g_table[NCLS * 4 * HID];   //  4 MB  layer0 pre-activation table
__device__ float g_pre1 [SEQ  * 4 * HID];   // 64 MB  layer1 pre
__device__ float g_pre2 [SEQ  * 4 * NCLS];  // 16 MB  layer2 pre
__device__ float g_hs0  [SEQ * HID];        // 16 MB  h0 (GEMM input)
__device__ float g_hs1  [SEQ * HID];        // 16 MB  h1 (GEMM input / finals)
__device__ ull   g_tg0  [SEQ * HID];        // 32 MB  tagged h0 handoff
__device__ ull   g_tg1  [SEQ * HID];        // 32 MB  tagged h1 handoff
__device__ ull   g_tg2  [SEQ * NCLS];       //  8 MB  tagged h2 handoff
__device__ float g_cfin [2 * HID + NCLS];   // c0, c1, c2 finals
__device__ unsigned int g_gen;

// ---------------- helpers ----------------
__device__ __forceinline__ float fsig(float x) {
    return __fdividef(1.0f, 1.0f + __expf(-x));
}
// exact-path tanh, register-lean: 2/(1+e^-2x) - 1 (saturates correctly)
__device__ __forceinline__ float ftanh(float x) {
    return __fdividef(2.0f, 1.0f + __expf(-2.0f * x)) - 1.0f;
}
__device__ __forceinline__ ull ld_tag(const ull* p) {
    ull v;
    asm volatile("ld.relaxed.gpu.global.b64 %0, [%1];" : "=l"(v) : "l"(p) : "memory");
    return v;
}
__device__ __forceinline__ void st_tag(ull* p, ull v) {
    asm volatile("st.relaxed.gpu.global.b64 [%0], %1;" :: "l"(p), "l"(v) : "memory");
}
// packed dual-fp32 FMA (B300 f32x2 pipe)
__device__ __forceinline__ ull fma2(ull a, ull b, ull c) {
    ull d;
    asm("fma.rn.f32x2 %0, %1, %2, %3;" : "=l"(d) : "l"(a), "l"(b), "l"(c));
    return d;
}
__device__ __forceinline__ float lo32(ull v) { return __uint_as_float((unsigned)v); }
__device__ __forceinline__ float hi32(ull v) { return __uint_as_float((unsigned)(v >> 32)); }

__global__ void bump_gen_kernel() { if (threadIdx.x == 0) g_gen += 1u; }

// ---------------- GEMM:  C[M][N] = A[M][K] @ B[N][K]^T + b1[N] + b2[N] -----
// 128x64 tile, 256 threads, 8x4 accumulators, 2-stage double-buffered SMEM:
// one __syncthreads per k-tile, global loads overlapped with compute.
template<int WHICH>
__global__ void __launch_bounds__(256)
gemm_bias(const float* __restrict__ Ain, const float* __restrict__ B,
          const float* __restrict__ b1, const float* __restrict__ b2,
          int M, int N, int K)
{
    const float* A = (WHICH == 1) ? g_hs0 : (WHICH == 2) ? g_hs1 : Ain;
    float*       C = (WHICH == 0) ? g_table : (WHICH == 1) ? g_pre1 : g_pre2;

    __shared__ float As[2][16][136];
    __shared__ float Bs[2][16][72];

    const int m0 = blockIdx.y * 128;
    const int n0 = blockIdx.x * 64;
    const int tid = threadIdx.x;
    const int tm = tid >> 4;
    const int tn = tid & 15;
    const int lra = tid >> 1;
    const int lka = (tid & 1) * 8;
    const int lrb = tid >> 2;
    const int lkb = (tid & 3) * 4;

    float acc[8][4];
#pragma unroll
    for (int i = 0; i < 8; i++)
#pragma unroll
        for (int j = 0; j < 4; j++) acc[i][j] = 0.0f;

    // stage 0 load
    {
        float4 a0 = *reinterpret_cast<const float4*>(&A[(size_t)(m0 + lra) * K + lka]);
        float4 a1 = *reinterpret_cast<const float4*>(&A[(size_t)(m0 + lra) * K + lka + 4]);
        float4 bv = *reinterpret_cast<const float4*>(&B[(size_t)(n0 + lrb) * K + lkb]);
        As[0][lka + 0][lra] = a0.x; As[0][lka + 1][lra] = a0.y; As[0][lka + 2][lra] = a0.z; As[0][lka + 3][lra] = a0.w;
        As[0][lka + 4][lra] = a1.x; As[0][lka + 5][lra] = a1.y; As[0][lka + 6][lra] = a1.z; As[0][lka + 7][lra] = a1.w;
        Bs[0][lkb + 0][lrb] = bv.x; Bs[0][lkb + 1][lrb] = bv.y; Bs[0][lkb + 2][lrb] = bv.z; Bs[0][lkb + 3][lrb] = bv.w;
    }
    __syncthreads();

    int buf = 0;
    for (int kt = 0; kt < K; kt += 16) {
        const bool more = (kt + 16) < K;
        float4 a0n, a1n, bvn;
        if (more) {
            a0n = *reinterpret_cast<const float4*>(&A[(size_t)(m0 + lra) * K + kt + 16 + lka]);
            a1n = *reinterpret_cast<const float4*>(&A[(size_t)(m0 + lra) * K + kt + 16 + lka + 4]);
            bvn = *reinterpret_cast<const float4*>(&B[(size_t)(n0 + lrb) * K + kt + 16 + lkb]);
        }
#pragma unroll
        for (int kk = 0; kk < 16; kk++) {
            float4 a4 = *reinterpret_cast<const float4*>(&As[buf][kk][tm * 8]);
            float4 a5 = *reinterpret_cast<const float4*>(&As[buf][kk][tm * 8 + 4]);
            float4 b4 = *reinterpret_cast<const float4*>(&Bs[buf][kk][tn * 4]);
            float a[8] = {a4.x, a4.y, a4.z, a4.w, a5.x, a5.y, a5.z, a5.w};
            float b[4] = {b4.x, b4.y, b4.z, b4.w};
#pragma unroll
            for (int i = 0; i < 8; i++)
#pragma unroll
                for (int j = 0; j < 4; j++) acc[i][j] += a[i] * b[j];
        }
        if (more) {
            const int nb = buf ^ 1;
            As[nb][lka + 0][lra] = a0n.x; As[nb][lka + 1][lra] = a0n.y; As[nb][lka + 2][lra] = a0n.z; As[nb][lka + 3][lra] = a0n.w;
            As[nb][lka + 4][lra] = a1n.x; As[nb][lka + 5][lra] = a1n.y; As[nb][lka + 6][lra] = a1n.z; As[nb][lka + 7][lra] = a1n.w;
            Bs[nb][lkb + 0][lrb] = bvn.x; Bs[nb][lkb + 1][lrb] = bvn.y; Bs[nb][lkb + 2][lrb] = bvn.z; Bs[nb][lkb + 3][lrb] = bvn.w;
            __syncthreads();
            buf = nb;
        }
    }

    const int col0 = n0 + tn * 4;
    float4 v1 = *reinterpret_cast<const float4*>(&b1[col0]);
    float4 v2 = *reinterpret_cast<const float4*>(&b2[col0]);
    float bias[4] = {v1.x + v2.x, v1.y + v2.y, v1.z + v2.z, v1.w + v2.w};
#pragma unroll
    for (int i = 0; i < 8; i++) {
        int row = m0 + tm * 8 + i;
        float4 o;
        o.x = acc[i][0] + bias[0];
        o.y = acc[i][1] + bias[1];
        o.z = acc[i][2] + bias[2];
        o.w = acc[i][3] + bias[3];
        *reinterpret_cast<float4*>(&C[(size_t)row * N + col0]) = o;
    }
}

// ---------------- LSTM scan (R3-proven structure, verbatim) ----------------
// 8 warps/CTA, warp w owns output (cta*8+w) = 4 gate rows; weights in regs.
// h_{t-1} handoff: 64-bit {tag,h} words in L2, batch-polled in parallel.
template<int INDIM, int OUTDIM, int LAYER>
__global__ void __launch_bounds__(256, 1)
lstm_scan(const float* __restrict__ whh,       // [4*OUTDIM][INDIM]
          const int*   __restrict__ tokens,    // layer 0 only
          float*       __restrict__ hs_param)  // layer 2: d_out
{
    constexpr int KITER = INDIM / 128;   // 8 (HID) or 2 (NCLS)
    constexpr int PPT   = INDIM / 256;   // tagged words staged per thread

    const float* pre = (LAYER == 0) ? g_table : (LAYER == 1) ? g_pre1 : g_pre2;
    ull*   tg = (LAYER == 0) ? g_tg0 : (LAYER == 1) ? g_tg1 : g_tg2;
    float* hs = (LAYER == 0) ? g_hs0 : (LAYER == 1) ? g_hs1 : hs_param;
    float* cf = g_cfin + ((LAYER == 0) ? 0 : (LAYER == 1) ? HID : 2 * HID);

    const int tid = threadIdx.x;
    const int w = tid >> 5;
    const int l = tid & 31;
    const int out = blockIdx.x * 8 + w;
    const unsigned tb = g_gen * (unsigned)(SEQ + 1);

    __shared__ __align__(16) float sh[2][INDIM];
    __shared__ int stok[(LAYER == 0) ? SEQ : 1];

    // register-resident weights: 4 gate rows, this lane's k-slices
    ulonglong2 wq[4][KITER];
#pragma unroll
    for (int r = 0; r < 4; r++)
#pragma unroll
        for (int i = 0; i < KITER; i++)
            wq[r][i] = *reinterpret_cast<const ulonglong2*>(
                whh + (size_t)(r * OUTDIM + out) * INDIM + i * 128 + 4 * l);

    if constexpr (LAYER == 0) {
        for (int i = tid; i < SEQ; i += 256) stok[i] = tokens[i];
    }
    for (int i = tid; i < INDIM; i += 256) sh[0][i] = 0.0f;
    __syncthreads();

    auto loadpre = [&](int tt, int r) -> float {
        if constexpr (LAYER == 0)
            return __ldg(&pre[(size_t)stok[tt] * (4 * OUTDIM) + r * OUTDIM + out]);
        else
            return __ldg(&pre[(size_t)tt * (4 * OUTDIM) + r * OUTDIM + out]);
    };

    float c = 0.0f;
    float pv = (l < 4) ? loadpre(0, l) : 0.0f;

    for (int t = 0; t < SEQ; t++) {
        float pvn = (l < 4 && t + 1 < SEQ) ? loadpre(t + 1, l) : 0.0f;

        float* shb = sh[t & 1];
        if (t > 0) {
            const ull* src = tg + (size_t)(t - 1) * INDIM;
            const unsigned expect = tb + (unsigned)t;   // producer wrote tb + (t-1) + 1
            ull v[PPT];
            // parallel batch poll: all PPT loads in flight simultaneously
#pragma unroll
            for (int j = 0; j < PPT; j++) v[j] = ld_tag(src + tid + 256 * j);
            while (true) {
                bool ok = true;
#pragma unroll
                for (int j = 0; j < PPT; j++) ok &= ((unsigned)(v[j] >> 32) == expect);
                if (ok) break;
#pragma unroll
                for (int j = 0; j < PPT; j++) v[j] = ld_tag(src + tid + 256 * j);
            }
#pragma unroll
            for (int j = 0; j < PPT; j++)
                shb[tid + 256 * j] = __uint_as_float((unsigned)v[j]);
        }
        __syncthreads();

        // 4 gate-row dot products, packed f32x2 FMA
        ull acc[4] = {0ull, 0ull, 0ull, 0ull};
#pragma unroll
        for (int i = 0; i < KITER; i++) {
            ulonglong2 hv = *reinterpret_cast<const ulonglong2*>(shb + i * 128 + 4 * l);
#pragma unroll
            for (int r = 0; r < 4; r++) {
                acc[r] = fma2(wq[r][i].x, hv.x, acc[r]);
                acc[r] = fma2(wq[r][i].y, hv.y, acc[r]);
            }
        }
        float g[4];
#pragma unroll
        for (int r = 0; r < 4; r++) g[r] = lo32(acc[r]) + hi32(acc[r]);
#pragma unroll
        for (int s = 16; s > 0; s >>= 1)
#pragma unroll
            for (int r = 0; r < 4; r++) g[r] += __shfl_xor_sync(0xffffffffu, g[r], s);

        const float p0 = __shfl_sync(0xffffffffu, pv, 0);
        const float p1 = __shfl_sync(0xffffffffu, pv, 1);
        const float p2 = __shfl_sync(0xffffffffu, pv, 2);
        const float p3 = __shfl_sync(0xffffffffu, pv, 3);

        c = fsig(g[1] + p1) * c + fsig(g[0] + p0) * ftanh(g[2] + p2);
        const float h = fsig(g[3] + p3) * ftanh(c);

        if (l == 0) {
            st_tag(tg + (size_t)t * OUTDIM + out,
                   ((ull)(tb + (unsigned)t + 1u) << 32) | (ull)__float_as_uint(h));
            hs[(size_t)t * OUTDIM + out] = h;
            if (t == SEQ - 1) cf[out] = c;
        }
        pv = pvn;
    }
}

// ---------------- final output assembly ----------------
__global__ void finalize_kernel(float* __restrict__ out) {
    int i = blockIdx.x * blockDim.x + threadIdx.x;
    const int OB = SEQ * NCLS;   // 1048576: start of h_stack
    if (i < 1024)      out[OB + i] = g_hs0[(SEQ - 1) * HID + i];
    else if (i < 2048) out[OB + i] = g_hs1[(SEQ - 1) * HID + (i - 1024)];
    else if (i < 3072) out[OB + i] = g_cfin[i - 2048];                   // c0
    else if (i < 4096) out[OB + i] = g_cfin[HID + (i - 3072)];           // c1
    else if (i < 4352) out[OB + i] = out[(SEQ - 1) * NCLS + (i - 4096)]; // h2
    else if (i < 4608) out[OB + i] = g_cfin[2 * HID + (i - 4352)];       // c2
}

// ---------------- launch ----------------
extern "C" void kernel_launch(void* const* d_in, const int* in_sizes, int n_in,
                              void* d_out, int out_size)
{
    const int*   tokens = (const int*)  d_in[0];
    const float* embed  = (const float*)d_in[1];
    const float* w_ih0  = (const float*)d_in[2];
    const float* w_hh0  = (const float*)d_in[3];
    const float* b_ih0  = (const float*)d_in[4];
    const float* b_hh0  = (const float*)d_in[5];
    const float* w_ih1  = (const float*)d_in[6];
    const float* w_hh1  = (const float*)d_in[7];
    const float* b_ih1  = (const float*)d_in[8];
    const float* b_hh1  = (const float*)d_in[9];
    const float* w_ih2  = (const float*)d_in[10];
    const float* w_hh2  = (const float*)d_in[11];
    const float* b_ih2  = (const float*)d_in[12];
    const float* b_hh2  = (const float*)d_in[13];
    float* out = (float*)d_out;

    bump_gen_kernel<<<1, 32>>>();

    // layer 0 pre-activation table: [256 classes][4096 gate rows]
    gemm_bias<0><<<dim3(4 * HID / 64, NCLS / 128), 256>>>(embed, w_ih0, b_ih0, b_hh0,
                                                          NCLS, 4 * HID, HID);
    lstm_scan<HID, HID, 0><<<HID / 8, 256>>>(w_hh0, tokens, nullptr);

    gemm_bias<1><<<dim3(4 * HID / 64, SEQ / 128), 256>>>(nullptr, w_ih1, b_ih1, b_hh1,
                                                         SEQ, 4 * HID, HID);
    lstm_scan<HID, HID, 1><<<HID / 8, 256>>>(w_hh1, nullptr, nullptr);

    gemm_bias<2><<<dim3(4 * NCLS / 64, SEQ / 128), 256>>>(nullptr, w_ih2, b_ih2, b_hh2,
                                                          SEQ, 4 * NCLS, HID);
    lstm_scan<NCLS, NCLS, 2><<<NCLS / 8, 256>>>(w_hh2, nullptr, out);

    finalize_kernel<<<18, 256>>>(out);
}